// round 4
// baseline (speedup 1.0000x reference)
#include <cuda_runtime.h>
#include <cuda_bf16.h>
#include <cuda_fp8.h>
#include <cstdint>
#include <math.h>

// C = normalize_rows(ex) @ normalize_rows(ey)^T  [8192 x 8192]
// rowmax/colmax -> entropy terms. FP8 (e4m3) mma.sync GEMM, inputs scaled by
// 16 (C scaled by 256, de-scaled in epilogue). C never materialized.

#define NROWS 8192
#define KDIM  768
#define BM 128
#define BN 256
#define BK 128                   // 128 fp8 = 128B rows
#define NK (KDIM / BK)           // 6
#define NSTAGE 4
#define A_BYTES (BM * BK)        // 16384
#define B_BYTES (BN * BK)        // 32768
#define STAGE_BYTES (A_BYTES + B_BYTES)    // 49152
#define SMEM_TOTAL (NSTAGE * STAGE_BYTES)  // 196608
#define FP8_SCALE 16.0f
#define INV_SCALE2 (1.0f / 256.0f)

__device__ __align__(128) unsigned char g_Xq[NROWS * KDIM];
__device__ __align__(128) unsigned char g_Yq[NROWS * KDIM];
__device__ float g_rowmax[NROWS];
__device__ float g_colmax[NROWS];

__device__ __forceinline__ void atomicMaxF(float* addr, float v) {
    if (v >= 0.f) atomicMax((int*)addr, __float_as_int(v));
    else          atomicMin((unsigned int*)addr, __float_as_uint(v));
}
__device__ __forceinline__ uint32_t s2u(const void* p) {
    return (uint32_t)__cvta_generic_to_shared(p);
}

// ---------------------------------------------------------------------------
// Kernel 1: row-normalize fp32 -> e4m3 (x16 scale)
// ---------------------------------------------------------------------------
__global__ __launch_bounds__(256) void norm_kernel(const float* __restrict__ ex,
                                                   const float* __restrict__ ey) {
    int b = blockIdx.x;
    const float* src;
    unsigned char* dst;
    if (b < NROWS) { src = ex + (size_t)b * KDIM; dst = g_Xq + (size_t)b * KDIM; }
    else           { b -= NROWS; src = ey + (size_t)b * KDIM; dst = g_Yq + (size_t)b * KDIM; }

    int tid = threadIdx.x;
    float4 v = make_float4(0.f, 0.f, 0.f, 0.f);
    float ss = 0.f;
    if (tid < 192) {
        v = ((const float4*)src)[tid];
        ss = v.x * v.x + v.y * v.y + v.z * v.z + v.w * v.w;
    }
    #pragma unroll
    for (int o = 16; o > 0; o >>= 1) ss += __shfl_xor_sync(0xffffffffu, ss, o);
    __shared__ float wsum[8];
    if ((tid & 31) == 0) wsum[tid >> 5] = ss;
    __syncthreads();
    float tot = wsum[0] + wsum[1] + wsum[2] + wsum[3] +
                wsum[4] + wsum[5] + wsum[6] + wsum[7];
    float inv = FP8_SCALE / fmaxf(sqrtf(tot), 1e-8f);
    if (tid < 192) {
        float2 lo = make_float2(v.x * inv, v.y * inv);
        float2 hi = make_float2(v.z * inv, v.w * inv);
        __nv_fp8x2_storage_t plo = __nv_cvt_float2_to_fp8x2(lo, __NV_SATFINITE, __NV_E4M3);
        __nv_fp8x2_storage_t phi = __nv_cvt_float2_to_fp8x2(hi, __NV_SATFINITE, __NV_E4M3);
        uint32_t packed = (uint32_t)plo | ((uint32_t)phi << 16);
        *(uint32_t*)(dst + tid * 4) = packed;
    }
}

__global__ void init_kernel() {
    int t = blockIdx.x * blockDim.x + threadIdx.x;
    if (t < NROWS) { g_rowmax[t] = -1e30f; g_colmax[t] = -1e30f; }
}

// ---------------------------------------------------------------------------
// Kernel 3: fp8 GEMM via mma.sync m16n8k32 + ldmatrix, 128x256 CTA tile,
// 64x64 warp tile, BK=128 (128B rows), 4-stage cp.async, fused row/col max.
// Swizzle: sw(row, kh) = row*128 + ((kh ^ (row & 7)) << 4), kh = 16B chunk.
// ---------------------------------------------------------------------------
__global__ __launch_bounds__(256, 1) void gemm_max_kernel() {
    extern __shared__ __align__(1024) char smem[];
    __shared__ float srow[BM];
    __shared__ float scol[BN];

    const int tid = threadIdx.x;
    const int warp = tid >> 5, lane = tid & 31;
    const int m0 = blockIdx.y * BM;
    const int n0 = blockIdx.x * BN;
    const int wm = (warp >> 2) * 64;
    const int wn = (warp & 3) * 64;

    if (tid < BM) srow[tid] = -1e30f;
    scol[tid] = -1e30f;

    float acc[4][8][4];
    #pragma unroll
    for (int a = 0; a < 4; a++)
        #pragma unroll
        for (int b = 0; b < 8; b++)
            #pragma unroll
            for (int c = 0; c < 4; c++) acc[a][b][c] = 0.f;

    auto prefetch = [&](int stage, int k0, bool valid) {
        if (valid) {
            char* sa = smem + stage * STAGE_BYTES;
            char* sb = sa + A_BYTES;
            #pragma unroll
            for (int j = 0; j < 12; j++) {
                int i = tid + j * 256;  // 16B chunks: A 1024, B 2048
                const unsigned char* src;
                uint32_t dst;
                if (i < 1024) {         // A: 128 rows x 8 chunks
                    int row = i >> 3, kh = i & 7;
                    src = g_Xq + (size_t)(m0 + row) * KDIM + k0 + kh * 16;
                    dst = s2u(sa + row * 128 + ((kh ^ (row & 7)) << 4));
                } else {                // B: 256 rows x 8 chunks
                    int idx = i - 1024;
                    int row = idx >> 3, kh = idx & 7;
                    src = g_Yq + (size_t)(n0 + row) * KDIM + k0 + kh * 16;
                    dst = s2u(sb + row * 128 + ((kh ^ (row & 7)) << 4));
                }
                asm volatile("cp.async.cg.shared.global [%0], [%1], 16;"
                             :: "r"(dst), "l"(src));
            }
        }
        asm volatile("cp.async.commit_group;");
    };

    prefetch(0, 0, true);
    prefetch(1, BK, true);
    prefetch(2, 2 * BK, true);

    for (int it = 0; it < NK; it++) {
        asm volatile("cp.async.wait_group 2;");
        __syncthreads();
        prefetch((it + 3) & 3, (it + 3) * BK, it + 3 < NK);

        const uint32_t sa = s2u(smem) + (uint32_t)(it & 3) * STAGE_BYTES;
        const uint32_t sb = sa + A_BYTES;

        #pragma unroll
        for (int kk = 0; kk < 4; kk++) {   // 4 x k32 per BK=128
            uint32_t af[4][4], bf[4][4];
            #pragma unroll
            for (int mt = 0; mt < 4; mt++) {
                int row = wm + mt * 16 + (lane & 15);
                int kh = kk * 2 + (lane >> 4);
                uint32_t addr = sa + row * 128 + ((kh ^ (row & 7)) << 4);
                asm volatile(
                    "ldmatrix.sync.aligned.m8n8.x4.shared.b16 {%0,%1,%2,%3}, [%4];"
                    : "=r"(af[mt][0]), "=r"(af[mt][1]),
                      "=r"(af[mt][2]), "=r"(af[mt][3]) : "r"(addr));
            }
            #pragma unroll
            for (int p = 0; p < 4; p++) {
                int n = wn + p * 16 + ((lane >> 4) << 3) + (lane & 7);
                int kh = kk * 2 + ((lane >> 3) & 1);
                uint32_t addr = sb + n * 128 + ((kh ^ (n & 7)) << 4);
                asm volatile(
                    "ldmatrix.sync.aligned.m8n8.x4.shared.b16 {%0,%1,%2,%3}, [%4];"
                    : "=r"(bf[p][0]), "=r"(bf[p][1]),
                      "=r"(bf[p][2]), "=r"(bf[p][3]) : "r"(addr));
            }
            #pragma unroll
            for (int mt = 0; mt < 4; mt++)
                #pragma unroll
                for (int nt = 0; nt < 8; nt++) {
                    asm volatile(
                        "mma.sync.aligned.m16n8k32.row.col.f32.e4m3.e4m3.f32 "
                        "{%0,%1,%2,%3}, {%4,%5,%6,%7}, {%8,%9}, {%0,%1,%2,%3};\n"
                        : "+f"(acc[mt][nt][0]), "+f"(acc[mt][nt][1]),
                          "+f"(acc[mt][nt][2]), "+f"(acc[mt][nt][3])
                        : "r"(af[mt][0]), "r"(af[mt][1]),
                          "r"(af[mt][2]), "r"(af[mt][3]),
                          "r"(bf[nt >> 1][(nt & 1) * 2]),
                          "r"(bf[nt >> 1][(nt & 1) * 2 + 1]));
                }
        }
    }
    __syncthreads();

    const int g = lane >> 2, tig = lane & 3;
    // ---- row maxes: row = wm + mt*16 + g + p*8 ----
    #pragma unroll
    for (int mt = 0; mt < 4; mt++)
        #pragma unroll
        for (int p = 0; p < 2; p++) {
            float m = -1e30f;
            #pragma unroll
            for (int nt = 0; nt < 8; nt++) {
                m = fmaxf(m, acc[mt][nt][p * 2 + 0]);
                m = fmaxf(m, acc[mt][nt][p * 2 + 1]);
            }
            m = fmaxf(m, __shfl_xor_sync(0xffffffffu, m, 1));
            m = fmaxf(m, __shfl_xor_sync(0xffffffffu, m, 2));
            if (tig == 0) atomicMaxF(&srow[wm + mt * 16 + g + p * 8], m * INV_SCALE2);
        }
    // ---- col maxes: col = wn + nt*8 + tig*2 + q ----
    #pragma unroll
    for (int nt = 0; nt < 8; nt++)
        #pragma unroll
        for (int q = 0; q < 2; q++) {
            float m = -1e30f;
            #pragma unroll
            for (int mt = 0; mt < 4; mt++) {
                m = fmaxf(m, acc[mt][nt][q]);
                m = fmaxf(m, acc[mt][nt][2 + q]);
            }
            m = fmaxf(m, __shfl_xor_sync(0xffffffffu, m, 4));
            m = fmaxf(m, __shfl_xor_sync(0xffffffffu, m, 8));
            m = fmaxf(m, __shfl_xor_sync(0xffffffffu, m, 16));
            if (g == 0) atomicMaxF(&scol[wn + nt * 8 + tig * 2 + q], m * INV_SCALE2);
        }

    __syncthreads();
    if (tid < BM) atomicMaxF(&g_rowmax[m0 + tid], srow[tid]);
    atomicMaxF(&g_colmax[n0 + tid], scol[tid]);
}

// ---------------------------------------------------------------------------
// Kernel 4: finalize entropy terms (1024 threads, fast exp).
// ---------------------------------------------------------------------------
__global__ __launch_bounds__(1024) void final_kernel(float* __restrict__ out) {
    const float LOG_NORM = -0.69579514f;  // -log(0.8) - 0.5*log(2*pi)
    const float INV2S2   = 0.78125f;      // 1 / (2 * 0.8^2)
    int tid = threadIdx.x;
    float s1 = 0.f, s2 = 0.f;
    for (int i = tid; i < NROWS; i += 1024) {
        float c = g_rowmax[i];
        float lp = -(c * c) * INV2S2 + LOG_NORM;
        s1 -= __expf(lp) * lp;
        c = g_colmax[i];
        lp = -(c * c) * INV2S2 + LOG_NORM;
        s2 -= __expf(lp) * lp;
    }
    #pragma unroll
    for (int o = 16; o > 0; o >>= 1) {
        s1 += __shfl_xor_sync(0xffffffffu, s1, o);
        s2 += __shfl_xor_sync(0xffffffffu, s2, o);
    }
    __shared__ float w1[32], w2[32];
    if ((tid & 31) == 0) { w1[tid >> 5] = s1; w2[tid >> 5] = s2; }
    __syncthreads();
    if (tid < 32) {
        float t1 = w1[tid], t2 = w2[tid];
        #pragma unroll
        for (int o = 16; o > 0; o >>= 1) {
            t1 += __shfl_xor_sync(0xffffffffu, t1, o);
            t2 += __shfl_xor_sync(0xffffffffu, t2, o);
        }
        if (tid == 0) { out[0] = t1; out[1] = t2; }
    }
}

// ---------------------------------------------------------------------------
extern "C" void kernel_launch(void* const* d_in, const int* in_sizes, int n_in,
                              void* d_out, int out_size) {
    (void)in_sizes; (void)n_in; (void)out_size;
    const float* ex = (const float*)d_in[0];
    const float* ey = (const float*)d_in[1];
    float* out = (float*)d_out;

    cudaFuncSetAttribute(gemm_max_kernel,
                         cudaFuncAttributeMaxDynamicSharedMemorySize, SMEM_TOTAL);

    norm_kernel<<<2 * NROWS, 256>>>(ex, ey);
    init_kernel<<<(NROWS + 255) / 256, 256>>>();
    dim3 grid(NROWS / BN, NROWS / BM);   // 32 x 64
    gemm_max_kernel<<<grid, 256, SMEM_TOTAL>>>();
    final_kernel<<<1, 1024>>>(out);
}

// round 5
// speedup vs baseline: 1.1362x; 1.1362x over previous
#include <cuda_runtime.h>
#include <cuda_bf16.h>
#include <cstdint>
#include <math.h>

// C = normalize_rows(ex) @ normalize_rows(ey)^T  [8192 x 8192]
// rowmax/colmax -> entropy terms. bf16 mma.sync GEMM, 512 threads/CTA
// (4 warps/SMSP to hide LDSM latency), C never materialized.

#define NROWS 8192
#define KDIM  768
#define BM 128
#define BN 256
#define BK 64                  // 64 bf16 = 128B rows
#define NK (KDIM / BK)         // 12
#define NSTAGE 4
#define A_BYTES (BM * BK * 2)  // 16384
#define B_BYTES (BN * BK * 2)  // 32768
#define STAGE_BYTES (A_BYTES + B_BYTES)       // 49152
#define SMEM_TOTAL (NSTAGE * STAGE_BYTES)     // 196608

__device__ __align__(128) __nv_bfloat16 g_Xn[NROWS * KDIM];
__device__ __align__(128) __nv_bfloat16 g_Yn[NROWS * KDIM];
__device__ float g_rowmax[NROWS];
__device__ float g_colmax[NROWS];

__device__ __forceinline__ void atomicMaxF(float* addr, float v) {
    if (v >= 0.f) atomicMax((int*)addr, __float_as_int(v));
    else          atomicMin((unsigned int*)addr, __float_as_uint(v));
}
__device__ __forceinline__ uint32_t s2u(const void* p) {
    return (uint32_t)__cvta_generic_to_shared(p);
}

// ---------------------------------------------------------------------------
// Kernel 1: row-normalize fp32 -> bf16
// ---------------------------------------------------------------------------
__global__ __launch_bounds__(256) void norm_kernel(const float* __restrict__ ex,
                                                   const float* __restrict__ ey) {
    int b = blockIdx.x;
    const float* src;
    __nv_bfloat16* dst;
    if (b < NROWS) { src = ex + (size_t)b * KDIM; dst = g_Xn + (size_t)b * KDIM; }
    else           { b -= NROWS; src = ey + (size_t)b * KDIM; dst = g_Yn + (size_t)b * KDIM; }

    int tid = threadIdx.x;
    float4 v = make_float4(0.f, 0.f, 0.f, 0.f);
    float ss = 0.f;
    if (tid < 192) {
        v = ((const float4*)src)[tid];
        ss = v.x * v.x + v.y * v.y + v.z * v.z + v.w * v.w;
    }
    #pragma unroll
    for (int o = 16; o > 0; o >>= 1) ss += __shfl_xor_sync(0xffffffffu, ss, o);
    __shared__ float wsum[8];
    if ((tid & 31) == 0) wsum[tid >> 5] = ss;
    __syncthreads();
    float tot = wsum[0] + wsum[1] + wsum[2] + wsum[3] +
                wsum[4] + wsum[5] + wsum[6] + wsum[7];
    float inv = 1.0f / fmaxf(sqrtf(tot), 1e-8f);
    if (tid < 192) {
        dst[tid * 4 + 0] = __float2bfloat16(v.x * inv);
        dst[tid * 4 + 1] = __float2bfloat16(v.y * inv);
        dst[tid * 4 + 2] = __float2bfloat16(v.z * inv);
        dst[tid * 4 + 3] = __float2bfloat16(v.w * inv);
    }
}

__global__ void init_kernel() {
    int t = blockIdx.x * blockDim.x + threadIdx.x;
    if (t < NROWS) { g_rowmax[t] = -2.f; g_colmax[t] = -2.f; }
}

// ---------------------------------------------------------------------------
// Kernel 3: bf16 GEMM, 128x256 CTA tile, 16 warps, 64x32 warp tile, BK=64,
// 4-stage cp.async pipeline, fused row/col max.
// Swizzle: sw(row, kh) = row*128 + ((kh ^ (row & 7)) << 4), kh = 16B chunk.
// ---------------------------------------------------------------------------
__global__ __launch_bounds__(512, 1) void gemm_max_kernel() {
    extern __shared__ __align__(1024) char smem[];
    __shared__ float srow[BM];
    __shared__ float scol[BN];

    const int tid = threadIdx.x;
    const int warp = tid >> 5, lane = tid & 31;
    const int m0 = blockIdx.y * BM;
    const int n0 = blockIdx.x * BN;
    const int wm = (warp >> 3) * 64;   // 0 or 64
    const int wn = (warp & 7) * 32;    // 0..224

    if (tid < BM) srow[tid] = -2.f;
    if (tid < BN) scol[tid] = -2.f;

    float acc[4][4][4];
    #pragma unroll
    for (int a = 0; a < 4; a++)
        #pragma unroll
        for (int b = 0; b < 4; b++)
            #pragma unroll
            for (int c = 0; c < 4; c++) acc[a][b][c] = 0.f;

    auto prefetch = [&](int stage, int k0, bool valid) {
        if (valid) {
            char* sa = smem + stage * STAGE_BYTES;
            char* sb = sa + A_BYTES;
            #pragma unroll
            for (int j = 0; j < 6; j++) {
                int i = tid + j * 512;  // 0..3071 chunks of 16B
                const __nv_bfloat16* src;
                uint32_t dst;
                if (i < 1024) {         // A: 128 rows x 8 chunks
                    int row = i >> 3, kh = i & 7;
                    src = g_Xn + (size_t)(m0 + row) * KDIM + k0 + kh * 8;
                    dst = s2u(sa + row * 128 + ((kh ^ (row & 7)) << 4));
                } else {                // B: 256 rows x 8 chunks
                    int idx = i - 1024;
                    int row = idx >> 3, kh = idx & 7;
                    src = g_Yn + (size_t)(n0 + row) * KDIM + k0 + kh * 8;
                    dst = s2u(sb + row * 128 + ((kh ^ (row & 7)) << 4));
                }
                asm volatile("cp.async.cg.shared.global [%0], [%1], 16;"
                             :: "r"(dst), "l"(src));
            }
        }
        asm volatile("cp.async.commit_group;");
    };

    prefetch(0, 0, true);
    prefetch(1, BK, true);
    prefetch(2, 2 * BK, true);

    for (int it = 0; it < NK; it++) {
        asm volatile("cp.async.wait_group 2;");
        __syncthreads();
        prefetch((it + 3) & 3, (it + 3) * BK, it + 3 < NK);

        const uint32_t sa = s2u(smem) + (uint32_t)(it & 3) * STAGE_BYTES;
        const uint32_t sb = sa + A_BYTES;

        #pragma unroll
        for (int kk = 0; kk < 4; kk++) {
            uint32_t af[4][4], bf[2][4];
            #pragma unroll
            for (int mt = 0; mt < 4; mt++) {
                int row = wm + mt * 16 + (lane & 15);
                int kh = kk * 2 + (lane >> 4);
                uint32_t addr = sa + row * 128 + ((kh ^ (row & 7)) << 4);
                asm volatile(
                    "ldmatrix.sync.aligned.m8n8.x4.shared.b16 {%0,%1,%2,%3}, [%4];"
                    : "=r"(af[mt][0]), "=r"(af[mt][1]),
                      "=r"(af[mt][2]), "=r"(af[mt][3]) : "r"(addr));
            }
            #pragma unroll
            for (int p = 0; p < 2; p++) {
                int n = wn + p * 16 + ((lane >> 4) << 3) + (lane & 7);
                int kh = kk * 2 + ((lane >> 3) & 1);
                uint32_t addr = sb + n * 128 + ((kh ^ (n & 7)) << 4);
                asm volatile(
                    "ldmatrix.sync.aligned.m8n8.x4.shared.b16 {%0,%1,%2,%3}, [%4];"
                    : "=r"(bf[p][0]), "=r"(bf[p][1]),
                      "=r"(bf[p][2]), "=r"(bf[p][3]) : "r"(addr));
            }
            #pragma unroll
            for (int mt = 0; mt < 4; mt++)
                #pragma unroll
                for (int nt = 0; nt < 4; nt++) {
                    asm volatile(
                        "mma.sync.aligned.m16n8k16.row.col.f32.bf16.bf16.f32 "
                        "{%0,%1,%2,%3}, {%4,%5,%6,%7}, {%8,%9}, {%0,%1,%2,%3};\n"
                        : "+f"(acc[mt][nt][0]), "+f"(acc[mt][nt][1]),
                          "+f"(acc[mt][nt][2]), "+f"(acc[mt][nt][3])
                        : "r"(af[mt][0]), "r"(af[mt][1]),
                          "r"(af[mt][2]), "r"(af[mt][3]),
                          "r"(bf[nt >> 1][(nt & 1) * 2]),
                          "r"(bf[nt >> 1][(nt & 1) * 2 + 1]));
                }
        }
    }
    __syncthreads();

    const int g = lane >> 2, tig = lane & 3;
    // ---- row maxes: row = wm + mt*16 + g + p*8 ----
    #pragma unroll
    for (int mt = 0; mt < 4; mt++)
        #pragma unroll
        for (int p = 0; p < 2; p++) {
            float m = -2.f;
            #pragma unroll
            for (int nt = 0; nt < 4; nt++) {
                m = fmaxf(m, acc[mt][nt][p * 2 + 0]);
                m = fmaxf(m, acc[mt][nt][p * 2 + 1]);
            }
            m = fmaxf(m, __shfl_xor_sync(0xffffffffu, m, 1));
            m = fmaxf(m, __shfl_xor_sync(0xffffffffu, m, 2));
            if (tig == 0) atomicMaxF(&srow[wm + mt * 16 + g + p * 8], m);
        }
    // ---- col maxes: col = wn + nt*8 + tig*2 + q ----
    #pragma unroll
    for (int nt = 0; nt < 4; nt++)
        #pragma unroll
        for (int q = 0; q < 2; q++) {
            float m = -2.f;
            #pragma unroll
            for (int mt = 0; mt < 4; mt++) {
                m = fmaxf(m, acc[mt][nt][q]);
                m = fmaxf(m, acc[mt][nt][2 + q]);
            }
            m = fmaxf(m, __shfl_xor_sync(0xffffffffu, m, 4));
            m = fmaxf(m, __shfl_xor_sync(0xffffffffu, m, 8));
            m = fmaxf(m, __shfl_xor_sync(0xffffffffu, m, 16));
            if (g == 0) atomicMaxF(&scol[wn + nt * 8 + tig * 2 + q], m);
        }

    __syncthreads();
    if (tid < BM) atomicMaxF(&g_rowmax[m0 + tid], srow[tid]);
    if (tid < BN) atomicMaxF(&g_colmax[n0 + tid], scol[tid]);
}

// ---------------------------------------------------------------------------
// Kernel 4: finalize entropy terms.
// ---------------------------------------------------------------------------
__global__ __launch_bounds__(1024) void final_kernel(float* __restrict__ out) {
    const float LOG_NORM = -0.69579514f;  // -log(0.8) - 0.5*log(2*pi)
    const float INV2S2   = 0.78125f;      // 1 / (2 * 0.8^2)
    int tid = threadIdx.x;
    float s1 = 0.f, s2 = 0.f;
    for (int i = tid; i < NROWS; i += 1024) {
        float c = g_rowmax[i];
        float lp = -(c * c) * INV2S2 + LOG_NORM;
        s1 -= __expf(lp) * lp;
        c = g_colmax[i];
        lp = -(c * c) * INV2S2 + LOG_NORM;
        s2 -= __expf(lp) * lp;
    }
    #pragma unroll
    for (int o = 16; o > 0; o >>= 1) {
        s1 += __shfl_xor_sync(0xffffffffu, s1, o);
        s2 += __shfl_xor_sync(0xffffffffu, s2, o);
    }
    __shared__ float w1[32], w2[32];
    if ((tid & 31) == 0) { w1[tid >> 5] = s1; w2[tid >> 5] = s2; }
    __syncthreads();
    if (tid < 32) {
        float t1 = w1[tid], t2 = w2[tid];
        #pragma unroll
        for (int o = 16; o > 0; o >>= 1) {
            t1 += __shfl_xor_sync(0xffffffffu, t1, o);
            t2 += __shfl_xor_sync(0xffffffffu, t2, o);
        }
        if (tid == 0) { out[0] = t1; out[1] = t2; }
    }
}

// ---------------------------------------------------------------------------
extern "C" void kernel_launch(void* const* d_in, const int* in_sizes, int n_in,
                              void* d_out, int out_size) {
    (void)in_sizes; (void)n_in; (void)out_size;
    const float* ex = (const float*)d_in[0];
    const float* ey = (const float*)d_in[1];
    float* out = (float*)d_out;

    cudaFuncSetAttribute(gemm_max_kernel,
                         cudaFuncAttributeMaxDynamicSharedMemorySize, SMEM_TOTAL);

    norm_kernel<<<2 * NROWS, 256>>>(ex, ey);
    init_kernel<<<(NROWS + 255) / 256, 256>>>();
    dim3 grid(NROWS / BN, NROWS / BM);   // 32 x 64
    gemm_max_kernel<<<grid, 512, SMEM_TOTAL>>>();
    final_kernel<<<1, 1024>>>(out);
}